// round 5
// baseline (speedup 1.0000x reference)
#include <cuda_runtime.h>

// Morphological opening (erosion then dilation) with 3x3 cross SE, fused.
// img: [24, 1024, 1024] float32 planes (B*C collapsed into grid.z).
// Border semantics match kornia: OOB neighbors never win min/max.

#define W 1024
#define H 1024
#define TILE_W 128
#define TILE_H 32
#define IN_W 132   // TILE_W + 2*2 halo
#define IN_H 36    // TILE_H + 2*2 halo
#define ER_W 130   // TILE_W + 2*1 halo
#define ER_H 34    // TILE_H + 2*1 halo
#define BIGV 1e4f

__global__ __launch_bounds__(256, 6)
void opening_kernel(const float* __restrict__ img, float* __restrict__ out)
{
    __shared__ float s_in[IN_H * IN_W];
    __shared__ float s_er[ER_H * ER_W];

    const int tx = threadIdx.x;          // 0..31
    const int ty = threadIdx.y;          // 0..7
    const int tid = ty * 32 + tx;        // 0..255

    const int x0 = blockIdx.x * TILE_W;
    const int y0 = blockIdx.y * TILE_H;
    const float* __restrict__ src = img + (size_t)blockIdx.z * (W * H);
    float* __restrict__ dst = out + (size_t)blockIdx.z * (W * H);

    // ---- Stage 1: load input tile (+2 halo) with +BIG padding ----
    #pragma unroll
    for (int i = tid; i < IN_W * IN_H; i += 256) {
        const int lx = i % IN_W;
        const int ly = i / IN_W;
        const int gx = x0 - 2 + lx;
        const int gy = y0 - 2 + ly;
        float v = BIGV;
        if ((unsigned)gx < (unsigned)W && (unsigned)gy < (unsigned)H)
            v = __ldg(src + gy * W + gx);
        s_in[ly * IN_W + lx] = v;
    }
    __syncthreads();

    // ---- Stage 2: erosion on the (+1 halo) region ----
    // e = min( vmin3(up,c,down), min(left,right) ); OOB erosion positions -> -BIG
    #pragma unroll
    for (int i = tid; i < ER_W * ER_H; i += 256) {
        const int ex = i % ER_W;
        const int ey = i / ER_W;
        const int gx = x0 - 1 + ex;
        const int gy = y0 - 1 + ey;
        float e;
        if ((unsigned)gx < (unsigned)W && (unsigned)gy < (unsigned)H) {
            const int c = (ey + 1) * IN_W + (ex + 1);
            float vm = fminf(fminf(s_in[c - IN_W], s_in[c]), s_in[c + IN_W]);
            float hm = fminf(s_in[c - 1], s_in[c + 1]);
            e = fminf(vm, hm);
        } else {
            e = -BIGV;  // ignored by the dilation max
        }
        s_er[ey * ER_W + ex] = e;
    }
    __syncthreads();

    // ---- Stage 3: dilation, float4 stores ----
    // Each thread: 4 consecutive x (tx*4..tx*4+3), 4 rows (ty, ty+8, ty+16, ty+24)
    const int oxb = tx * 4;
    #pragma unroll
    for (int k = 0; k < 4; k++) {
        const int ry = ty + k * 8;              // tile-local output row
        const int ecy = ry + 1;                 // erosion-tile center row
        float4 r;
        float* rp = &r.x;
        #pragma unroll
        for (int c = 0; c < 4; c++) {
            const int ecx = oxb + c + 1;        // erosion-tile center col
            const int ci = ecy * ER_W + ecx;
            float vm = fmaxf(fmaxf(s_er[ci - ER_W], s_er[ci]), s_er[ci + ER_W]);
            float hm = fmaxf(s_er[ci - 1], s_er[ci + 1]);
            rp[c] = fmaxf(vm, hm);
        }
        *reinterpret_cast<float4*>(dst + (size_t)(y0 + ry) * W + x0 + oxb) = r;
    }
}

extern "C" void kernel_launch(void* const* d_in, const int* in_sizes, int n_in,
                              void* d_out, int out_size)
{
    const float* img = (const float*)d_in[0];
    float* out = (float*)d_out;
    const int planes = in_sizes[0] / (W * H);   // 8*3 = 24

    dim3 block(32, 8, 1);
    dim3 grid(W / TILE_W, H / TILE_H, planes);  // 8 x 32 x 24
    opening_kernel<<<grid, block>>>(img, out);
}

// round 6
// speedup vs baseline: 2.1543x; 2.1543x over previous
#include <cuda_runtime.h>

// Morphological opening (erosion -> dilation), 3x3 CROSS structuring element.
// img: [24, 1024, 1024] fp32 planes. Kornia border semantics: OOB neighbors
// never win (erosion pad +1e4, dilation sees -1e4 at OOB erosion positions).
//
// Register-resident rolling-row pipeline, zero shared memory:
//   - each lane owns 4 columns (float4); a warp owns 128 cols x STRIP_H rows
//   - horizontal neighbors via warp shuffles; warp-edge columns via a few
//     predicated scalar loads + 1 extra scalar erosion column per edge lane.

#define W 1024
#define H 1024
#define STRIP_H 32
#define BIGV 1e4f
#define FULL 0xffffffffu

__device__ __forceinline__ float fmin3(float a, float b, float c) { return fminf(fminf(a, b), c); }
__device__ __forceinline__ float fmax3(float a, float b, float c) { return fmaxf(fmaxf(a, b), c); }

struct Ero { float4 e; float eL, eR; };

// Erosion of row t. a,b,c = input rows t-1,t,t+1 (4 owned cols).
// l1*/r1* = scalar input col just left/right of owned range (rows t-1,t,t+1);
// l2b/r2b = scalar input 2 cols out, row t. eL/eR = erosion at the edge cols.
__device__ __forceinline__ Ero ero_row(
    float4 a, float4 b, float4 c,
    float l1a, float l1b, float l1c, float l2b,
    float r1a, float r1b, float r1c, float r2b,
    bool isL, bool isR, bool okColL, bool okColR, bool rowValid)
{
    float lw = __shfl_up_sync(FULL, b.w, 1);
    if (isL) lw = l1b;
    float rw = __shfl_down_sync(FULL, b.x, 1);
    if (isR) rw = r1b;

    Ero o;
    o.e.x = fminf(fmin3(a.x, b.x, c.x), fminf(lw, b.y));
    o.e.y = fminf(fmin3(a.y, b.y, c.y), fminf(b.x, b.z));
    o.e.z = fminf(fmin3(a.z, b.z, c.z), fminf(b.y, b.w));
    o.e.w = fminf(fmin3(a.w, b.w, c.w), fminf(b.z, rw));
    o.eL = okColL ? fminf(fmin3(l1a, l1b, l1c), fminf(l2b, b.x)) : -BIGV;
    o.eR = okColR ? fminf(fmin3(r1a, r1b, r1c), fminf(b.w, r2b)) : -BIGV;
    if (!rowValid) {
        o.e = make_float4(-BIGV, -BIGV, -BIGV, -BIGV);
        o.eL = -BIGV; o.eR = -BIGV;
    }
    return o;
}

__global__ __launch_bounds__(256, 4)
void opening_kernel(const float* __restrict__ img, float* __restrict__ out)
{
    const int lane = threadIdx.x & 31;
    const int warp = threadIdx.x >> 5;
    const int gx = warp * 128 + lane * 4;       // first of 4 owned columns
    const int ys = blockIdx.y * STRIP_H;
    const size_t plane = (size_t)blockIdx.z * (size_t)(W * H);
    const float* __restrict__ src = img + plane;
    float* __restrict__ dst = out + plane;

    const bool isL = (lane == 0);
    const bool isR = (lane == 31);
    const int colL1 = gx - 1, colL2 = gx - 2;
    const int colR1 = gx + 4, colR2 = gx + 5;
    const bool okL1 = isL && (colL1 >= 0);
    const bool okL2 = isL && (colL2 >= 0);
    const bool okR1 = isR && (colR1 < W);
    const bool okR2 = isR && (colR2 < W);

    auto loadv = [&](int row) -> float4 {
        if ((unsigned)row < (unsigned)H)
            return *reinterpret_cast<const float4*>(src + (size_t)row * W + gx);
        return make_float4(BIGV, BIGV, BIGV, BIGV);
    };
    auto loads = [&](int row, int col, bool ok) -> float {
        return (ok && (unsigned)row < (unsigned)H) ? src[(size_t)row * W + col] : BIGV;
    };

    // ---- Prologue: input rows ys-2 .. ys+1 ----
    float4 A = loadv(ys - 2), B = loadv(ys - 1), C = loadv(ys), D = loadv(ys + 1);
    float l1A = loads(ys - 2, colL1, okL1), l1B = loads(ys - 1, colL1, okL1);
    float l1C = loads(ys,     colL1, okL1), l1D = loads(ys + 1, colL1, okL1);
    float r1A = loads(ys - 2, colR1, okR1), r1B = loads(ys - 1, colR1, okR1);
    float r1C = loads(ys,     colR1, okR1), r1D = loads(ys + 1, colR1, okR1);
    float l2B = loads(ys - 1, colL2, okL2), l2C = loads(ys, colL2, okL2), l2D = loads(ys + 1, colL2, okL2);
    float r2B = loads(ys - 1, colR2, okR2), r2C = loads(ys, colR2, okR2), r2D = loads(ys + 1, colR2, okR2);

    Ero ep = ero_row(A, B, C, l1A, l1B, l1C, l2B, r1A, r1B, r1C, r2B,
                     isL, isR, okL1, okR1, (ys - 1) >= 0);          // e(ys-1)
    Ero ec = ero_row(B, C, D, l1B, l1C, l1D, l2C, r1B, r1C, r1D, r2C,
                     isL, isR, okL1, okR1, true);                    // e(ys)

    float4 e_prev = ep.e, e_cur = ec.e;
    float  eL_cur = ec.eL, eR_cur = ec.eR;
    float4 in_a = C, in_b = D;
    float  l1_a = l1C, l1_b = l1D, l2_b = l2D;
    float  r1_a = r1C, r1_b = r1D, r2_b = r2D;

    // ---- Main loop: one output row per iteration ----
    #pragma unroll 4
    for (int y = ys; y < ys + STRIP_H; ++y) {
        const int rn = y + 2;
        float4 in_c = loadv(rn);
        float  l1_c = loads(rn, colL1, okL1);
        float  l2_c = loads(rn, colL2, okL2);
        float  r1_c = loads(rn, colR1, okR1);
        float  r2_c = loads(rn, colR2, okR2);

        Ero en = ero_row(in_a, in_b, in_c, l1_a, l1_b, l1_c, l2_b,
                         r1_a, r1_b, r1_c, r2_b,
                         isL, isR, okL1, okR1, (y + 1) < H);         // e(y+1)

        // Dilation at row y
        float lwE = __shfl_up_sync(FULL, e_cur.w, 1);
        if (isL) lwE = eL_cur;
        float rwE = __shfl_down_sync(FULL, e_cur.x, 1);
        if (isR) rwE = eR_cur;

        float4 d;
        d.x = fmaxf(fmax3(e_prev.x, e_cur.x, en.e.x), fmaxf(lwE,     e_cur.y));
        d.y = fmaxf(fmax3(e_prev.y, e_cur.y, en.e.y), fmaxf(e_cur.x, e_cur.z));
        d.z = fmaxf(fmax3(e_prev.z, e_cur.z, en.e.z), fmaxf(e_cur.y, e_cur.w));
        d.w = fmaxf(fmax3(e_prev.w, e_cur.w, en.e.w), fmaxf(e_cur.z, rwE));

        *reinterpret_cast<float4*>(dst + (size_t)y * W + gx) = d;

        // Shift pipeline
        e_prev = e_cur; e_cur = en.e;
        eL_cur = en.eL; eR_cur = en.eR;
        in_a = in_b; in_b = in_c;
        l1_a = l1_b; l1_b = l1_c; l2_b = l2_c;
        r1_a = r1_b; r1_b = r1_c; r2_b = r2_c;
    }
}

extern "C" void kernel_launch(void* const* d_in, const int* in_sizes, int n_in,
                              void* d_out, int out_size)
{
    const float* img = (const float*)d_in[0];
    float* out = (float*)d_out;
    const int planes = in_sizes[0] / (W * H);   // 8*3 = 24

    dim3 block(256, 1, 1);                      // 8 warps x 128 cols = full row
    dim3 grid(1, H / STRIP_H, planes);          // 1 x 32 x 24 = 768 blocks
    opening_kernel<<<grid, block>>>(img, out);
}

// round 7
// speedup vs baseline: 2.4488x; 1.1367x over previous
#include <cuda_runtime.h>

// Morphological opening (erosion -> dilation), 3x3 CROSS structuring element.
// img: [24, 1024, 1024] fp32 planes. Kornia border semantics: OOB neighbors
// never win (erosion pad +1e4; OOB erosion positions contribute -1e4 to max).
//
// Register-resident rolling-row pipeline, zero shared memory.
// Each lane owns 4 cols (float4); warp owns 128 cols; 8 warps cover the row.
// Horizontal neighbors via warp shuffle; each warp-edge lane additionally
// tracks exactly ONE adjacent column (c1, pipelined) + loads c2 on demand.

#define W 1024
#define H 1024
#define STRIP_H 16
#define BIGV 1e4f
#define FULL 0xffffffffu

__device__ __forceinline__ float fmin3(float a, float b, float c) { return fminf(fminf(a, b), c); }
__device__ __forceinline__ float fmax3(float a, float b, float c) { return fmaxf(fmaxf(a, b), c); }

__global__ __launch_bounds__(256, 5)
void opening_kernel(const float* __restrict__ img, float* __restrict__ out)
{
    const int lane = threadIdx.x & 31;
    const int warp = threadIdx.x >> 5;
    const int gx = warp * 128 + lane * 4;       // first of 4 owned columns
    const int ys = blockIdx.y * STRIP_H;
    const size_t plane = (size_t)blockIdx.z * (size_t)(W * H);
    const float* __restrict__ src = img + plane;
    float* __restrict__ dst = out + plane;

    const bool isL = (lane == 0);
    const bool isR = (lane == 31);
    const bool isEdge = isL | isR;
    // The single adjacent column this edge lane is responsible for:
    const int c1 = isL ? gx - 1 : gx + 4;
    const int c2 = isL ? gx - 2 : gx + 5;
    const bool ok1 = isEdge && ((unsigned)c1 < (unsigned)W);
    const bool ok2 = isEdge && ((unsigned)c2 < (unsigned)W);

    auto loadv = [&](int row) -> float4 {
        if ((unsigned)row < (unsigned)H)
            return *reinterpret_cast<const float4*>(src + (size_t)row * W + gx);
        return make_float4(BIGV, BIGV, BIGV, BIGV);
    };
    auto loadsc = [&](int row, int col, bool ok) -> float {
        return (ok && (unsigned)row < (unsigned)H) ? __ldg(src + (size_t)row * W + col) : BIGV;
    };

    // ---- Prologue: input rows ys-2 .. ys+1 ----
    float4 A  = loadv(ys - 2);
    float4 Bv = loadv(ys - 1);
    float4 C  = loadv(ys);
    float4 D  = loadv(ys + 1);
    float s1B = loadsc(ys - 1, c1, ok1);
    float s1C = loadsc(ys,     c1, ok1);
    float s1D = loadsc(ys + 1, c1, ok1);
    float s2C = loadsc(ys,     c2, ok2);

    // e(ys-1): owned columns only (its edge value is never needed)
    float4 e_prev;
    {
        float lw = __shfl_up_sync(FULL, Bv.w, 1);   if (isL) lw = s1B;
        float rw = __shfl_down_sync(FULL, Bv.x, 1); if (isR) rw = s1B;
        e_prev.x = fminf(fmin3(A.x, Bv.x, C.x), fminf(lw,   Bv.y));
        e_prev.y = fminf(fmin3(A.y, Bv.y, C.y), fminf(Bv.x, Bv.z));
        e_prev.z = fminf(fmin3(A.z, Bv.z, C.z), fminf(Bv.y, Bv.w));
        e_prev.w = fminf(fmin3(A.w, Bv.w, C.w), fminf(Bv.z, rw));
        if (ys - 1 < 0) e_prev = make_float4(-BIGV, -BIGV, -BIGV, -BIGV);
    }

    // e(ys): owned columns + edge column
    float4 e_cur;
    float  eEdge_cur;
    {
        float lw = __shfl_up_sync(FULL, C.w, 1);   if (isL) lw = s1C;
        float rw = __shfl_down_sync(FULL, C.x, 1); if (isR) rw = s1C;
        e_cur.x = fminf(fmin3(Bv.x, C.x, D.x), fminf(lw,  C.y));
        e_cur.y = fminf(fmin3(Bv.y, C.y, D.y), fminf(C.x, C.z));
        e_cur.z = fminf(fmin3(Bv.z, C.z, D.z), fminf(C.y, C.w));
        e_cur.w = fminf(fmin3(Bv.w, C.w, D.w), fminf(C.z, rw));
        float X = isL ? C.x : C.w;
        eEdge_cur = ok1 ? fminf(fmin3(s1B, s1C, s1D), fminf(s2C, X)) : -BIGV;
    }

    // Rolling state: rows (y, y+1) for the iteration computing e(y+1)
    float4 in_a = C, in_b = D;
    float  s1_a = s1C, s1_b = s1D;

    // ---- Main loop: one output row per iteration ----
    #pragma unroll 4
    for (int y = ys; y < ys + STRIP_H; ++y) {
        const int rn = y + 2;
        float4 in_c = loadv(rn);
        float  s1_c = loadsc(rn,    c1, ok1);
        float  s2m  = loadsc(y + 1, c2, ok2);

        // Erosion at row y+1
        float4 en;
        float  eEdgeN;
        {
            float lw = __shfl_up_sync(FULL, in_b.w, 1);   if (isL) lw = s1_b;
            float rw = __shfl_down_sync(FULL, in_b.x, 1); if (isR) rw = s1_b;
            en.x = fminf(fmin3(in_a.x, in_b.x, in_c.x), fminf(lw,     in_b.y));
            en.y = fminf(fmin3(in_a.y, in_b.y, in_c.y), fminf(in_b.x, in_b.z));
            en.z = fminf(fmin3(in_a.z, in_b.z, in_c.z), fminf(in_b.y, in_b.w));
            en.w = fminf(fmin3(in_a.w, in_b.w, in_c.w), fminf(in_b.z, rw));
            float X = isL ? in_b.x : in_b.w;
            eEdgeN = ok1 ? fminf(fmin3(s1_a, s1_b, s1_c), fminf(s2m, X)) : -BIGV;
            if (y + 1 >= H) {
                en = make_float4(-BIGV, -BIGV, -BIGV, -BIGV);
                eEdgeN = -BIGV;
            }
        }

        // Dilation at row y
        float lwE = __shfl_up_sync(FULL, e_cur.w, 1);   if (isL) lwE = eEdge_cur;
        float rwE = __shfl_down_sync(FULL, e_cur.x, 1); if (isR) rwE = eEdge_cur;

        float4 d;
        d.x = fmaxf(fmax3(e_prev.x, e_cur.x, en.x), fmaxf(lwE,     e_cur.y));
        d.y = fmaxf(fmax3(e_prev.y, e_cur.y, en.y), fmaxf(e_cur.x, e_cur.z));
        d.z = fmaxf(fmax3(e_prev.z, e_cur.z, en.z), fmaxf(e_cur.y, e_cur.w));
        d.w = fmaxf(fmax3(e_prev.w, e_cur.w, en.w), fmaxf(e_cur.z, rwE));

        *reinterpret_cast<float4*>(dst + (size_t)y * W + gx) = d;

        // Shift pipeline
        e_prev = e_cur; e_cur = en; eEdge_cur = eEdgeN;
        in_a = in_b; in_b = in_c;
        s1_a = s1_b; s1_b = s1_c;
    }
}

extern "C" void kernel_launch(void* const* d_in, const int* in_sizes, int n_in,
                              void* d_out, int out_size)
{
    const float* img = (const float*)d_in[0];
    float* out = (float*)d_out;
    const int planes = in_sizes[0] / (W * H);   // 8*3 = 24

    dim3 block(256, 1, 1);                      // 8 warps x 128 cols = full row
    dim3 grid(1, H / STRIP_H, planes);          // 1 x 64 x 24 = 1536 blocks
    opening_kernel<<<grid, block>>>(img, out);
}